// round 9
// baseline (speedup 1.0000x reference)
#include <cuda_runtime.h>
#include <math.h>

#define NN 110
#define XS 122      // Xh row stride (XmT rows, then h1 rows)
#define FHS 2860    // feats per-head stride: rows of 26 floats (gcd(26,32)=2 -> ~2-way LDS)
#define WHS 2644    // W1s per-head stride (verbatim rows of 24, 16B aligned)
#define ENS 112     // per-head stride for en1/en2
#define NT 576
#define ALPHA 0.2f

typedef unsigned long long u64;

__device__ __forceinline__ u64 ffma2(u64 a, u64 b, u64 c) {
    u64 d; asm("fma.rn.f32x2 %0, %1, %2, %3;" : "=l"(d) : "l"(a), "l"(b), "l"(c)); return d;
}
__device__ __forceinline__ u64 splat2(float x) {
    u64 d; asm("mov.b64 %0, {%1, %1};" : "=l"(d) : "f"(x)); return d;
}
__device__ __forceinline__ float2 unpack2(u64 v) {
    float2 r; asm("mov.b64 {%0, %1}, %2;" : "=f"(r.x), "=f"(r.y) : "l"(v)); return r;
}
__device__ __forceinline__ float lrelu(float v) { return v > 0.f ? v : ALPHA * v; }
__device__ __forceinline__ float sigm(float v) { return 1.f / (1.f + __expf(-v)); }
__device__ __forceinline__ float warp_sum(float v) {
#pragma unroll
    for (int o = 16; o > 0; o >>= 1) v += __shfl_xor_sync(0xffffffffu, v, o);
    return v;
}
__device__ __forceinline__ float warp_max(float v) {
#pragma unroll
    for (int o = 16; o > 0; o >>= 1) v = fmaxf(v, __shfl_xor_sync(0xffffffffu, v, o));
    return v;
}

// ---- smem layout (float offsets); all 16B-vector bases %4==0 ----
#define OFF_XH    0         // 13420
#define OFF_FEATS 13420     // 14300 = 5*FHS (rows of 26)
#define OFF_W1S   27720     // 13220 = 5*WHS
#define OFF_W2C   40940     // 1488 = 12*124
#define OFF_F2S   42428     // 1320
#define OFF_HP    43748     // 1320
#define OFF_ES1   45068     // 552
#define OFF_EN1   45620     // 560
#define OFF_ES2   46180     // 332
#define OFF_EN2   46512     // 336
#define OFF_AS1   46848     // 120
#define OFF_AN1   46968     // 120
#define OFF_B1    47088     // 24
#define OFF_AS2   47112     // 12
#define OFF_AN2   47124     // 12
#define OFF_B2    47136     // 4
#define OFF_FC1   47140     // 4
#define OFF_TS    47144     // 112
#define OFF_US    47256     // 112
#define OFF_AM    47368     // 440 uints
#define SMEM_FLOATS (OFF_AM + 440)
#define SMEM_BYTES (SMEM_FLOATS * 4)

__global__ __launch_bounds__(NT, 1)
void gatmil_kernel(const float* __restrict__ X, const float* __restrict__ A,
                   const float* __restrict__ M,
                   const float* __restrict__ W1, const float* __restrict__ as1,
                   const float* __restrict__ an1, const float* __restrict__ b1,
                   const float* __restrict__ W2, const float* __restrict__ as2,
                   const float* __restrict__ an2, const float* __restrict__ b2,
                   const float* __restrict__ fc1, const float* __restrict__ fc2,
                   float* __restrict__ out)
{
    extern __shared__ float sm[];
    float* Xh    = sm + OFF_XH;      // XmT during P0-P1; h1 rows from P2 on
    float* feats = sm + OFF_FEATS;   // [h][n][26] (24 used)
    float* W1s   = sm + OFF_W1S;     // [h][i][24]
    float* W2c   = sm + OFF_W2C;
    float* f2s   = sm + OFF_F2S;
    float* hp    = sm + OFF_HP;
    float* es1   = sm + OFF_ES1;
    float* en1   = sm + OFF_EN1;
    float* es2   = sm + OFF_ES2;
    float* en2   = sm + OFF_EN2;
    float* as1s  = sm + OFF_AS1;
    float* an1s  = sm + OFF_AN1;
    float* b1s   = sm + OFF_B1;
    float* as2s  = sm + OFF_AS2;
    float* an2s  = sm + OFF_AN2;
    float* b2s   = sm + OFF_B2;
    float* fc1s  = sm + OFF_FC1;
    float* ts    = sm + OFF_TS;
    float* us    = sm + OFF_US;
    unsigned* Amask = (unsigned*)(sm + OFF_AM);

    const int b = blockIdx.x;
    const int tid = threadIdx.x;
    const int lane = tid & 31;
    const int wid = tid >> 5;

    const float* Xb = X + (size_t)b * NN * NN;
    const float* Ab = A + (size_t)b * NN * NN;

    // ================= P0: stage =================
    for (int h = 0; h < 5; h++)
        for (int j = tid; j < 2640; j += NT)
            W1s[h * WHS + j] = W1[h * 2640 + j];
    for (int i = tid; i < 120; i += NT) { as1s[i] = as1[i]; an1s[i] = an1[i]; }
    if (tid < 24) b1s[tid] = b1[tid];
    for (int idx = tid; idx < 12 * 124; idx += NT) {
        int c = idx / 124, k = idx - c * 124;
        int h2 = c >> 2, f2 = c & 3;
        float v = 0.f;
        if (k < 120 && f2 < 3) v = W2[(h2 * 120 + k) * 3 + f2];
        W2c[idx] = v;
    }
    if (tid < 9) { as2s[tid] = as2[tid]; an2s[tid] = an2[tid]; }
    if (tid < 3) { b2s[tid] = b2[tid]; fc1s[tid] = fc1[tid]; }
    // XmT[i][n] = X[n][i] * sigmoid(M[n][i])
    for (int n = wid; n < NN; n += NT / 32)
        for (int i = lane; i < NN; i += 32)
            Xh[i * XS + n] = Xb[n * NN + i] * sigm(M[n * NN + i]);
    // adjacency bitmask (pad bits >=110 are 0)
    for (int w = wid; w < NN * 4; w += NT / 32) {
        int n = w >> 2, seg = w & 3;
        int m = seg * 32 + lane;
        float a = (m < NN) ? Ab[n * NN + m] : 0.f;
        unsigned bal = __ballot_sync(0xffffffffu, a > 0.f);
        if (lane == 0) Amask[w] = bal;
    }
    __syncthreads();

    // ========== P1: feats = Xm @ W1, row-per-thread (550 thr) + fused logits ==========
    if (tid < 550) {
        const int h = tid / NN, n = tid - h * NN;
        const float* wb = W1s + h * WHS;
        const float* xcol = Xh + n;
        u64 acc[12];
#pragma unroll
        for (int j = 0; j < 12; j++) acc[j] = 0ull;
#pragma unroll 2
        for (int i = 0; i < NN; i++) {
            u64 s = splat2(xcol[i * XS]);
            const ulonglong2* w = (const ulonglong2*)(wb + i * 24);
            ulonglong2 w0 = w[0], w1 = w[1], w2 = w[2], w3 = w[3], w4 = w[4], w5 = w[5];
            acc[0]  = ffma2(s, w0.x, acc[0]);  acc[1]  = ffma2(s, w0.y, acc[1]);
            acc[2]  = ffma2(s, w1.x, acc[2]);  acc[3]  = ffma2(s, w1.y, acc[3]);
            acc[4]  = ffma2(s, w2.x, acc[4]);  acc[5]  = ffma2(s, w2.y, acc[5]);
            acc[6]  = ffma2(s, w3.x, acc[6]);  acc[7]  = ffma2(s, w3.y, acc[7]);
            acc[8]  = ffma2(s, w4.x, acc[8]);  acc[9]  = ffma2(s, w4.y, acc[9]);
            acc[10] = ffma2(s, w5.x, acc[10]); acc[11] = ffma2(s, w5.y, acc[11]);
        }
        u64* frow = (u64*)(feats + h * FHS + n * 26);   // rows of 26, base even
#pragma unroll
        for (int j = 0; j < 12; j++) frow[j] = acc[j];
        const u64* ap = (const u64*)(as1s + h * 24);
        const u64* np = (const u64*)(an1s + h * 24);
        u64 sa = 0ull, sb = 0ull;
#pragma unroll
        for (int j = 0; j < 12; j++) {
            sa = ffma2(acc[j], ap[j], sa);
            sb = ffma2(acc[j], np[j], sb);
        }
        float2 fa = unpack2(sa), fb2 = unpack2(sb);
        es1[tid] = fa.x + fa.y;
        en1[h * ENS + n] = fb2.x + fb2.y;
    }
    __syncthreads();

    // ========== P2: SPARSE fused softmax + aggregation (skip non-neighbors) ==========
    if (tid < 550) {
        const int h = tid / NN, n = tid - h * NN;
        const float es = es1[tid];
        const float* enh = en1 + h * ENS;
        const float* fbase = feats + h * FHS;
        u64 acc[12];
#pragma unroll
        for (int j = 0; j < 12; j++) acc[j] = 0ull;
        float sum = 0.f;
#pragma unroll
        for (int k = 0; k < 4; k++) {
            unsigned mw = Amask[n * 4 + k];
            while (mw) {
                const int m2 = __ffs(mw) - 1;
                mw &= (mw - 1);
                const int m = k * 32 + m2;
                float v = es + enh[m];
                v = v > 0.f ? v : ALPHA * v;
                const float e = __expf(v);
                sum += e;
                const u64 s = splat2(e);
                const u64* w = (const u64*)(fbase + m * 26);
#pragma unroll
                for (int j = 0; j < 12; j++) acc[j] = ffma2(s, w[j], acc[j]);
            }
        }
        const float rinv = 1.f / sum;   // self-loop guarantees sum > 0
        float* dst = Xh + n * XS + h * 24;   // h1 row n (XmT dead)
        // b1 shape [24], shared across heads
#pragma unroll
        for (int j = 0; j < 12; j++) {
            float2 p = unpack2(acc[j]);
            p.x = lrelu(fmaf(p.x, rinv, b1s[2 * j]));
            p.y = lrelu(fmaf(p.y, rinv, b1s[2 * j + 1]));
            *(float2*)(dst + 2 * j) = p;
        }
    }
    __syncthreads();

    // ================= P3: f2s = h1 @ W2 =================
    for (int idx = tid; idx < NN * 12; idx += NT) {
        int n = idx / 12, c = idx - n * 12;
        const u64* xr = (const u64*)(Xh + n * XS);
        const ulonglong2* wr = (const ulonglong2*)(W2c + c * 124);
        u64 acc0 = 0ull, acc1 = 0ull;
#pragma unroll 5
        for (int j = 0; j < 60; j += 2) {
            ulonglong2 wv = wr[j >> 1];
            acc0 = ffma2(xr[j], wv.x, acc0);
            acc1 = ffma2(xr[j + 1], wv.y, acc1);
        }
        float2 v0 = unpack2(acc0), v1 = unpack2(acc1);
        f2s[(c >> 2) * (NN * 4) + n * 4 + (c & 3)] = (v0.x + v0.y) + (v1.x + v1.y);
    }
    __syncthreads();

    // ================= P3b: layer-2 logit halves =================
    if (tid < 330) {
        int h2 = tid / NN, n = tid - h2 * NN;
        float4 fv = *(const float4*)(f2s + tid * 4);
        es2[tid] = fv.x * as2s[h2 * 3] + fv.y * as2s[h2 * 3 + 1] + fv.z * as2s[h2 * 3 + 2];
        en2[h2 * ENS + n] = fv.x * an2s[h2 * 3] + fv.y * an2s[h2 * 3 + 1] + fv.z * an2s[h2 * 3 + 2];
    }
    __syncthreads();

    // ========== P4: SPARSE fused layer-2 softmax + aggregation ==========
    if (tid < 330) {
        const int h2 = tid / NN, n = tid - h2 * NN;
        const float es = es2[tid];
        const float* enh = en2 + h2 * ENS;
        const ulonglong2* fbw = (const ulonglong2*)(f2s + h2 * (NN * 4));
        u64 a0 = 0ull, a1 = 0ull;
        float sum = 0.f;
#pragma unroll
        for (int k = 0; k < 4; k++) {
            unsigned mw = Amask[n * 4 + k];
            while (mw) {
                const int m2 = __ffs(mw) - 1;
                mw &= (mw - 1);
                const int m = k * 32 + m2;
                float v = es + enh[m];
                v = v > 0.f ? v : ALPHA * v;
                const float e = __expf(v);
                sum += e;
                const u64 s = splat2(e);
                ulonglong2 w = fbw[m];
                a0 = ffma2(s, w.x, a0);
                a1 = ffma2(s, w.y, a1);
            }
        }
        const float rinv = 1.f / sum;
        float2 v0 = unpack2(a0), v1 = unpack2(a1);
        float4 o; o.x = v0.x * rinv; o.y = v0.y * rinv; o.z = v1.x * rinv; o.w = 0.f;
        *(float4*)(hp + tid * 4) = o;
    }
    __syncthreads();

    // ================= P5: node probs =================
    if (tid < NN) {
        float4 p0 = *(const float4*)(hp + tid * 4);
        float4 p1 = *(const float4*)(hp + (NN + tid) * 4);
        float4 p2 = *(const float4*)(hp + (2 * NN + tid) * 4);
        float z = lrelu(fmaf((p0.x + p1.x + p2.x), (1.f / 3.f), b2s[0])) * fc1s[0]
                + lrelu(fmaf((p0.y + p1.y + p2.y), (1.f / 3.f), b2s[1])) * fc1s[1]
                + lrelu(fmaf((p0.z + p1.z + p2.z), (1.f / 3.f), b2s[2])) * fc1s[2];
        ts[tid] = sigm(z);
    }
    __syncthreads();

    // ================= P6: MIL pooling =================
    if (tid < 448) {
        int m = tid >> 2, q = tid & 3;
        float s = 0.f;
        if (m < NN) {
            int n0 = q * 28, n1 = n0 + 28 < NN ? n0 + 28 : NN;
            for (int n = n0; n < n1; n++) s = fmaf(ts[n], fc2[n * NN + m], s);
        }
        s += __shfl_xor_sync(0xffffffffu, s, 1);
        s += __shfl_xor_sync(0xffffffffu, s, 2);
        if (q == 0 && m < NN) us[m] = s;
    }
    __syncthreads();
    if (wid == 0) {
        float vmax = -3.4e38f;
        for (int m = lane; m < NN; m += 32) vmax = fmaxf(vmax, us[m]);
        vmax = warp_max(vmax);
        float num = 0.f, den = 0.f;
        for (int m = lane; m < NN; m += 32) {
            float e = __expf(us[m] - vmax);
            num = fmaf(ts[m], e, num);
            den += e;
        }
        num = warp_sum(num);
        den = warp_sum(den);
        if (lane == 0) out[b] = num / den;
    }
}

extern "C" void kernel_launch(void* const* d_in, const int* in_sizes, int n_in,
                              void* d_out, int out_size)
{
    const float* X   = (const float*)d_in[0];
    const float* A   = (const float*)d_in[1];
    const float* M   = (const float*)d_in[2];
    const float* W1  = (const float*)d_in[3];
    const float* as1 = (const float*)d_in[4];
    const float* an1 = (const float*)d_in[5];
    const float* b1  = (const float*)d_in[6];
    const float* W2  = (const float*)d_in[7];
    const float* as2 = (const float*)d_in[8];
    const float* an2 = (const float*)d_in[9];
    const float* b2  = (const float*)d_in[10];
    const float* fc1 = (const float*)d_in[11];
    const float* fc2 = (const float*)d_in[12];
    float* out = (float*)d_out;

    const int B = in_sizes[0] / (NN * NN);

    cudaFuncSetAttribute(gatmil_kernel, cudaFuncAttributeMaxDynamicSharedMemorySize, SMEM_BYTES);
    gatmil_kernel<<<B, NT, SMEM_BYTES>>>(X, A, M, W1, as1, an1, b1,
                                         W2, as2, an2, b2, fc1, fc2, out);
}

// round 10
// speedup vs baseline: 1.2098x; 1.2098x over previous
#include <cuda_runtime.h>
#include <math.h>

#define NN 110
#define BMAX 2048
#define ALPHA 0.2f

typedef unsigned long long u64;

__device__ __forceinline__ u64 ffma2(u64 a, u64 b, u64 c) {
    u64 d; asm("fma.rn.f32x2 %0, %1, %2, %3;" : "=l"(d) : "l"(a), "l"(b), "l"(c)); return d;
}
__device__ __forceinline__ u64 splat2(float x) {
    u64 d; asm("mov.b64 %0, {%1, %1};" : "=l"(d) : "f"(x)); return d;
}
__device__ __forceinline__ float2 unpack2(u64 v) {
    float2 r; asm("mov.b64 {%0, %1}, %2;" : "=f"(r.x), "=f"(r.y) : "l"(v)); return r;
}
__device__ __forceinline__ float lrelu(float v) { return v > 0.f ? v : ALPHA * v; }
__device__ __forceinline__ float sigm(float v) { return 1.f / (1.f + __expf(-v)); }
__device__ __forceinline__ float warp_sum(float v) {
#pragma unroll
    for (int o = 16; o > 0; o >>= 1) v += __shfl_xor_sync(0xffffffffu, v, o);
    return v;
}
__device__ __forceinline__ float warp_max(float v) {
#pragma unroll
    for (int o = 16; o > 0; o >>= 1) v = fmaxf(v, __shfl_xor_sync(0xffffffffu, v, o));
    return v;
}

// ---- global scratch (static __device__, no allocation) ----
__device__ float    g_xmT[(size_t)BMAX * 12100];   // [b][i][n]  99 MB
__device__ float    g_feats[(size_t)BMAX * 5 * 2640]; // [b][h][n][24] 108 MB
__device__ float    g_es1[BMAX * 5 * 112];
__device__ float    g_en1[BMAX * 5 * 112];
__device__ float    g_h1T[(size_t)BMAX * 13200];   // [b][k=h*24+f][n] 108 MB
__device__ float    g_f2s[BMAX * 1320];            // [b][h2][n][4]
__device__ float    g_es2[BMAX * 336];             // [b][h2*112+n]
__device__ float    g_en2[BMAX * 336];
__device__ unsigned g_am[BMAX * 440];              // [b][n][4]

// ================= K1: Xm transpose + adjacency masks =================
__global__ __launch_bounds__(256)
void k_prep(const float* __restrict__ X, const float* __restrict__ M,
            const float* __restrict__ A)
{
    __shared__ __align__(16) float tile[110 * 111];
    const int b = blockIdx.x, tid = threadIdx.x, lane = tid & 31, wid = tid >> 5;
    const float* Xb = X + (size_t)b * 12100;
    const float* Ab = A + (size_t)b * 12100;
    for (int idx = tid; idx < 12100; idx += 256) {
        int n = idx / NN, i = idx - n * NN;
        tile[i * 111 + n] = Xb[idx] * sigm(M[idx]);
    }
    for (int w = wid; w < 440; w += 8) {   // 55 iters per warp, no divergence
        int n = w >> 2, seg = w & 3;
        int m = seg * 32 + lane;
        float a = (m < NN) ? Ab[n * NN + m] : 0.f;
        unsigned bal = __ballot_sync(0xffffffffu, a > 0.f);
        if (lane == 0) g_am[b * 440 + w] = bal;
    }
    __syncthreads();
    float* dst = g_xmT + (size_t)b * 12100;
    for (int idx = tid; idx < 12100; idx += 256) {
        int i = idx / NN, n = idx - i * NN;
        dst[idx] = tile[i * 111 + n];   // LDS stride-1, STG coalesced
    }
}

// ================= K2: feats = Xm @ W1 + logit halves, CTA per (b,h) =================
__global__ __launch_bounds__(128, 6)
void k_feat(const float* __restrict__ W1, const float* __restrict__ as1,
            const float* __restrict__ an1)
{
    __shared__ __align__(16) float w1s[2640];
    const int b = blockIdx.x, h = blockIdx.y, tid = threadIdx.x;
    const float* wsrc = W1 + h * 2640;
    for (int idx = tid; idx < 2640; idx += 128) w1s[idx] = wsrc[idx];
    __syncthreads();
    if (tid < NN) {
        const int n = tid;
        const float* xp = g_xmT + (size_t)b * 12100 + n;
        u64 acc[12];
#pragma unroll
        for (int j = 0; j < 12; j++) acc[j] = 0ull;
#pragma unroll 5
        for (int i = 0; i < NN; i++) {
            u64 s = splat2(xp[i * NN]);          // coalesced LDG, L2-resident
            const ulonglong2* w = (const ulonglong2*)(w1s + i * 24);
            ulonglong2 w0 = w[0], w1_ = w[1], w2 = w[2], w3 = w[3], w4 = w[4], w5 = w[5];
            acc[0]  = ffma2(s, w0.x,  acc[0]);  acc[1]  = ffma2(s, w0.y,  acc[1]);
            acc[2]  = ffma2(s, w1_.x, acc[2]);  acc[3]  = ffma2(s, w1_.y, acc[3]);
            acc[4]  = ffma2(s, w2.x,  acc[4]);  acc[5]  = ffma2(s, w2.y,  acc[5]);
            acc[6]  = ffma2(s, w3.x,  acc[6]);  acc[7]  = ffma2(s, w3.y,  acc[7]);
            acc[8]  = ffma2(s, w4.x,  acc[8]);  acc[9]  = ffma2(s, w4.y,  acc[9]);
            acc[10] = ffma2(s, w5.x,  acc[10]); acc[11] = ffma2(s, w5.y,  acc[11]);
        }
        u64* fr = (u64*)(g_feats + ((size_t)(b * 5 + h) * NN + n) * 24);  // 96B-mult -> 8B aligned
#pragma unroll
        for (int j = 0; j < 12; j++) fr[j] = acc[j];
        const u64* ap = (const u64*)(as1 + h * 24);
        const u64* np = (const u64*)(an1 + h * 24);
        u64 sa = 0ull, sb = 0ull;
#pragma unroll
        for (int j = 0; j < 12; j++) {
            sa = ffma2(acc[j], ap[j], sa);
            sb = ffma2(acc[j], np[j], sb);
        }
        float2 fa = unpack2(sa), fb = unpack2(sb);
        g_es1[(b * 5 + h) * 112 + n] = fa.x + fa.y;
        g_en1[(b * 5 + h) * 112 + n] = fb.x + fb.y;
    }
}

// ================= K3: layer-1 sparse softmax+aggregation, CTA per (b,h) =================
__global__ __launch_bounds__(128, 6)
void k_attn1(const float* __restrict__ b1)
{
    __shared__ __align__(16) float fs[110 * 26 + 4];
    __shared__ float ens[112];
    __shared__ unsigned ams[440];
    const int b = blockIdx.x, h = blockIdx.y, tid = threadIdx.x;
    const float* fsrc = g_feats + (size_t)(b * 5 + h) * 2640;
    for (int idx = tid; idx < 2640; idx += 128) {
        int n = idx / 24, j = idx - n * 24;
        fs[n * 26 + j] = fsrc[idx];
    }
    for (int idx = tid; idx < NN; idx += 128) ens[idx] = g_en1[(b * 5 + h) * 112 + idx];
    for (int idx = tid; idx < 440; idx += 128) ams[idx] = g_am[b * 440 + idx];
    __syncthreads();
    if (tid < NN) {
        const int n = tid;
        const float es = g_es1[(b * 5 + h) * 112 + n];
        u64 acc[12];
#pragma unroll
        for (int j = 0; j < 12; j++) acc[j] = 0ull;
        float sum = 0.f;
#pragma unroll
        for (int k = 0; k < 4; k++) {
            unsigned mw = ams[n * 4 + k];
            while (mw) {
                const int m2 = __ffs(mw) - 1;
                mw &= (mw - 1);
                const int m = k * 32 + m2;
                float v = es + ens[m];
                v = v > 0.f ? v : ALPHA * v;
                const float e = __expf(v);
                sum += e;
                const u64 s = splat2(e);
                const u64* w = (const u64*)(fs + m * 26);   // 104B-mult -> 8B aligned
#pragma unroll
                for (int j = 0; j < 12; j++) acc[j] = ffma2(s, w[j], acc[j]);
            }
        }
        const float rinv = 1.f / sum;   // self-loop => sum > 0
        float* dst = g_h1T + (size_t)b * 13200 + (h * 24) * NN + n;
#pragma unroll
        for (int j = 0; j < 12; j++) {
            float2 p = unpack2(acc[j]);
            dst[(2 * j) * NN]     = lrelu(fmaf(p.x, rinv, b1[2 * j]));       // b1 shared across heads
            dst[(2 * j + 1) * NN] = lrelu(fmaf(p.y, rinv, b1[2 * j + 1]));
        }
    }
}

// ================= K4: layer-2 projection + logit halves, CTA per b =================
__global__ __launch_bounds__(128, 8)
void k_proj2(const float* __restrict__ W2, const float* __restrict__ as2,
             const float* __restrict__ an2)
{
    __shared__ float w2s[1080];
    __shared__ float a2s[9], n2s[9];
    const int b = blockIdx.x, tid = threadIdx.x;
    for (int idx = tid; idx < 1080; idx += 128) w2s[idx] = W2[idx];
    if (tid < 9) { a2s[tid] = as2[tid]; n2s[tid] = an2[tid]; }
    __syncthreads();
    if (tid < NN) {
        float acc[9];
#pragma unroll
        for (int j = 0; j < 9; j++) acc[j] = 0.f;
        const float* xp = g_h1T + (size_t)b * 13200 + tid;
#pragma unroll 4
        for (int k = 0; k < 120; k++) {
            float xv = xp[k * NN];               // coalesced LDG
#pragma unroll
            for (int h2 = 0; h2 < 3; h2++) {
#pragma unroll
                for (int f2 = 0; f2 < 3; f2++)
                    acc[h2 * 3 + f2] = fmaf(xv, w2s[h2 * 360 + k * 3 + f2], acc[h2 * 3 + f2]);
            }
        }
#pragma unroll
        for (int h2 = 0; h2 < 3; h2++) {
            float e_s = 0.f, e_n = 0.f;
#pragma unroll
            for (int f2 = 0; f2 < 3; f2++) {
                e_s = fmaf(acc[h2 * 3 + f2], a2s[h2 * 3 + f2], e_s);
                e_n = fmaf(acc[h2 * 3 + f2], n2s[h2 * 3 + f2], e_n);
            }
            g_es2[b * 336 + h2 * 112 + tid] = e_s;
            g_en2[b * 336 + h2 * 112 + tid] = e_n;
            float4 o; o.x = acc[h2 * 3]; o.y = acc[h2 * 3 + 1]; o.z = acc[h2 * 3 + 2]; o.w = 0.f;
            *(float4*)(g_f2s + ((size_t)(b * 3 + h2) * NN + tid) * 4) = o;
        }
    }
}

// ================= K5: layer-2 attn + node probs + MIL pooling, CTA per b =================
__global__ __launch_bounds__(128, 6)
void k_tail(const float* __restrict__ b2, const float* __restrict__ fc1,
            const float* __restrict__ fc2, float* __restrict__ out)
{
    __shared__ __align__(16) float f2sl[1320];
    __shared__ float en2s[336];
    __shared__ unsigned ams[440];
    __shared__ float tss[112], uss[112];
    const int b = blockIdx.x, tid = threadIdx.x, lane = tid & 31, wid = tid >> 5;
    for (int idx = tid; idx < 1320; idx += 128) f2sl[idx] = g_f2s[b * 1320 + idx];
    for (int idx = tid; idx < 336; idx += 128) en2s[idx] = g_en2[b * 336 + idx];
    for (int idx = tid; idx < 440; idx += 128) ams[idx] = g_am[b * 440 + idx];
    __syncthreads();
    if (tid < NN) {
        const int n = tid;
        float tot0 = 0.f, tot1 = 0.f, tot2 = 0.f;
#pragma unroll
        for (int h2 = 0; h2 < 3; h2++) {
            const float es = g_es2[b * 336 + h2 * 112 + n];
            const float* ens = en2s + h2 * 112;
            const ulonglong2* fbw = (const ulonglong2*)(f2sl + h2 * 440);
            u64 a0 = 0ull, a1 = 0ull;
            float sum = 0.f;
#pragma unroll
            for (int k = 0; k < 4; k++) {
                unsigned mw = ams[n * 4 + k];
                while (mw) {
                    const int m2 = __ffs(mw) - 1;
                    mw &= (mw - 1);
                    const int m = k * 32 + m2;
                    float v = es + ens[m];
                    v = v > 0.f ? v : ALPHA * v;
                    const float e = __expf(v);
                    sum += e;
                    const u64 s = splat2(e);
                    ulonglong2 w = fbw[m];
                    a0 = ffma2(s, w.x, a0);
                    a1 = ffma2(s, w.y, a1);
                }
            }
            const float rinv = 1.f / sum;
            float2 v0 = unpack2(a0), v1 = unpack2(a1);
            tot0 = fmaf(v0.x, rinv, tot0);
            tot1 = fmaf(v0.y, rinv, tot1);
            tot2 = fmaf(v1.x, rinv, tot2);
        }
        float z = lrelu(fmaf(tot0, (1.f / 3.f), b2[0])) * fc1[0]
                + lrelu(fmaf(tot1, (1.f / 3.f), b2[1])) * fc1[1]
                + lrelu(fmaf(tot2, (1.f / 3.f), b2[2])) * fc1[2];
        tss[tid] = sigm(z);
    }
    __syncthreads();
    if (tid < NN) {
        const int m = tid;
        float s = 0.f;
#pragma unroll 4
        for (int n2 = 0; n2 < NN; n2++) s = fmaf(tss[n2], fc2[n2 * NN + m], s);
        uss[m] = s;
    }
    __syncthreads();
    if (wid == 0) {
        float vmax = -3.4e38f;
        for (int m = lane; m < NN; m += 32) vmax = fmaxf(vmax, uss[m]);
        vmax = warp_max(vmax);
        float num = 0.f, den = 0.f;
        for (int m = lane; m < NN; m += 32) {
            float e = __expf(uss[m] - vmax);
            num = fmaf(tss[m], e, num);
            den += e;
        }
        num = warp_sum(num);
        den = warp_sum(den);
        if (lane == 0) out[b] = num / den;
    }
}

extern "C" void kernel_launch(void* const* d_in, const int* in_sizes, int n_in,
                              void* d_out, int out_size)
{
    const float* X   = (const float*)d_in[0];
    const float* A   = (const float*)d_in[1];
    const float* M   = (const float*)d_in[2];
    const float* W1  = (const float*)d_in[3];
    const float* as1 = (const float*)d_in[4];
    const float* an1 = (const float*)d_in[5];
    const float* b1  = (const float*)d_in[6];
    const float* W2  = (const float*)d_in[7];
    const float* as2 = (const float*)d_in[8];
    const float* an2 = (const float*)d_in[9];
    const float* b2  = (const float*)d_in[10];
    const float* fc1 = (const float*)d_in[11];
    const float* fc2 = (const float*)d_in[12];
    float* out = (float*)d_out;

    const int B = in_sizes[0] / (NN * NN);

    k_prep<<<B, 256>>>(X, M, A);
    k_feat<<<dim3(B, 5), 128>>>(W1, as1, an1);
    k_attn1<<<dim3(B, 5), 128>>>(b1);
    k_proj2<<<B, 128>>>(W2, as2, an2);
    k_tail<<<B, 128>>>(b2, fc1, fc2, out);
}

// round 11
// speedup vs baseline: 1.2640x; 1.0449x over previous
#include <cuda_runtime.h>
#include <math.h>

#define NN 110
#define ALPHA 0.2f

typedef unsigned long long u64;

__device__ __forceinline__ u64 ffma2(u64 a, u64 b, u64 c) {
    u64 d; asm("fma.rn.f32x2 %0, %1, %2, %3;" : "=l"(d) : "l"(a), "l"(b), "l"(c)); return d;
}
__device__ __forceinline__ u64 splat2(float x) {
    u64 d; asm("mov.b64 %0, {%1, %1};" : "=l"(d) : "f"(x)); return d;
}
__device__ __forceinline__ float2 unpack2(u64 v) {
    float2 r; asm("mov.b64 {%0, %1}, %2;" : "=f"(r.x), "=f"(r.y) : "l"(v)); return r;
}
__device__ __forceinline__ float lrelu(float v) { return v > 0.f ? v : ALPHA * v; }
__device__ __forceinline__ float sigm(float v) { return 1.f / (1.f + __expf(-v)); }
__device__ __forceinline__ float warp_sum(float v) {
#pragma unroll
    for (int o = 16; o > 0; o >>= 1) v += __shfl_xor_sync(0xffffffffu, v, o);
    return v;
}
__device__ __forceinline__ float warp_max(float v) {
#pragma unroll
    for (int o = 16; o > 0; o >>= 1) v = fmaxf(v, __shfl_xor_sync(0xffffffffu, v, o));
    return v;
}

// ---- global scratch ----
#define BMAX 2048
__device__ float    g_xmT[(size_t)BMAX * 12100];   // [b][i][n]
__device__ float    g_h1T[(size_t)BMAX * 13200];   // [b][k=h*24+f][n]
__device__ unsigned g_am[BMAX * 440];              // [b][n][4]

// ================= K1: Xm transpose + adjacency masks =================
__global__ __launch_bounds__(256)
void k_prep(const float* __restrict__ X, const float* __restrict__ M,
            const float* __restrict__ A)
{
    __shared__ __align__(16) float tile[110 * 111];
    const int b = blockIdx.x, tid = threadIdx.x, lane = tid & 31, wid = tid >> 5;
    const float* Xb = X + (size_t)b * 12100;
    const float* Ab = A + (size_t)b * 12100;
    for (int idx = tid; idx < 12100; idx += 256) {
        int n = idx / NN, i = idx - n * NN;
        tile[i * 111 + n] = Xb[idx] * sigm(M[idx]);
    }
    for (int w = wid; w < 440; w += 8) {
        int n = w >> 2, seg = w & 3;
        int m = seg * 32 + lane;
        float a = (m < NN) ? Ab[n * NN + m] : 0.f;
        unsigned bal = __ballot_sync(0xffffffffu, a > 0.f);
        if (lane == 0) g_am[b * 440 + w] = bal;
    }
    __syncthreads();
    float* dst = g_xmT + (size_t)b * 12100;
    for (int idx = tid; idx < 12100; idx += 256) {
        int i = idx / NN, n = idx - i * NN;
        dst[idx] = tile[i * 111 + n];
    }
}

// ====== K2 (fused): feats GEMM + logits + sparse softmax-aggregation, CTA per (b,h) ======
__global__ __launch_bounds__(128, 5)
void k_layer1(const float* __restrict__ W1, const float* __restrict__ as1,
              const float* __restrict__ an1, const float* __restrict__ b1)
{
    __shared__ __align__(16) float w1s[2640];
    __shared__ __align__(16) float fs[110 * 26 + 4];
    __shared__ float ess[112], ens[112];
    __shared__ unsigned ams[440];
    const int b = blockIdx.x, h = blockIdx.y, tid = threadIdx.x;

    const float* wsrc = W1 + h * 2640;
    for (int idx = tid; idx < 2640; idx += 128) w1s[idx] = wsrc[idx];
    for (int idx = tid; idx < 440; idx += 128) ams[idx] = g_am[b * 440 + idx];
    __syncthreads();

    // --- stage A: feats column-thread GEMM (R10 k_feat inner, verbatim) ---
    if (tid < NN) {
        const int n = tid;
        const float* xp = g_xmT + (size_t)b * 12100 + n;
        u64 acc[12];
#pragma unroll
        for (int j = 0; j < 12; j++) acc[j] = 0ull;
#pragma unroll 5
        for (int i = 0; i < NN; i++) {
            u64 s = splat2(xp[i * NN]);
            const ulonglong2* w = (const ulonglong2*)(w1s + i * 24);
            ulonglong2 w0 = w[0], w1_ = w[1], w2 = w[2], w3 = w[3], w4 = w[4], w5 = w[5];
            acc[0]  = ffma2(s, w0.x,  acc[0]);  acc[1]  = ffma2(s, w0.y,  acc[1]);
            acc[2]  = ffma2(s, w1_.x, acc[2]);  acc[3]  = ffma2(s, w1_.y, acc[3]);
            acc[4]  = ffma2(s, w2.x,  acc[4]);  acc[5]  = ffma2(s, w2.y,  acc[5]);
            acc[6]  = ffma2(s, w3.x,  acc[6]);  acc[7]  = ffma2(s, w3.y,  acc[7]);
            acc[8]  = ffma2(s, w4.x,  acc[8]);  acc[9]  = ffma2(s, w4.y,  acc[9]);
            acc[10] = ffma2(s, w5.x,  acc[10]); acc[11] = ffma2(s, w5.y,  acc[11]);
        }
        u64* fr = (u64*)(fs + n * 26);        // rows of 26, base even -> 8B aligned
#pragma unroll
        for (int j = 0; j < 12; j++) fr[j] = acc[j];
        const u64* ap = (const u64*)(as1 + h * 24);
        const u64* np = (const u64*)(an1 + h * 24);
        u64 sa = 0ull, sb = 0ull;
#pragma unroll
        for (int j = 0; j < 12; j++) {
            sa = ffma2(acc[j], ap[j], sa);
            sb = ffma2(acc[j], np[j], sb);
        }
        float2 fa = unpack2(sa), fb = unpack2(sb);
        ess[n] = fa.x + fa.y;
        ens[n] = fb.x + fb.y;
    }
    __syncthreads();

    // --- stage B: sparse softmax + aggregation (R10 k_attn1 inner, verbatim) ---
    if (tid < NN) {
        const int n = tid;
        const float es = ess[n];
        u64 acc[12];
#pragma unroll
        for (int j = 0; j < 12; j++) acc[j] = 0ull;
        float sum = 0.f;
#pragma unroll
        for (int k = 0; k < 4; k++) {
            unsigned mw = ams[n * 4 + k];
            while (mw) {
                const int m2 = __ffs(mw) - 1;
                mw &= (mw - 1);
                const int m = k * 32 + m2;
                float v = es + ens[m];
                v = v > 0.f ? v : ALPHA * v;
                const float e = __expf(v);
                sum += e;
                const u64 s = splat2(e);
                const u64* w = (const u64*)(fs + m * 26);
#pragma unroll
                for (int j = 0; j < 12; j++) acc[j] = ffma2(s, w[j], acc[j]);
            }
        }
        const float rinv = 1.f / sum;          // self-loop => sum > 0
        float* dst = g_h1T + (size_t)b * 13200 + (h * 24) * NN + n;
#pragma unroll
        for (int j = 0; j < 12; j++) {
            float2 p = unpack2(acc[j]);
            dst[(2 * j) * NN]     = lrelu(fmaf(p.x, rinv, b1[2 * j]));     // b1 shared across heads
            dst[(2 * j + 1) * NN] = lrelu(fmaf(p.y, rinv, b1[2 * j + 1]));
        }
    }
}

// ====== K3 (fused): layer-2 projection + attention + node probs + MIL, CTA per b ======
__global__ __launch_bounds__(128, 6)
void k_layer2(const float* __restrict__ W2, const float* __restrict__ as2,
              const float* __restrict__ an2, const float* __restrict__ b2,
              const float* __restrict__ fc1, const float* __restrict__ fc2,
              float* __restrict__ out)
{
    __shared__ float w2s[1080];
    __shared__ float a2s[9], n2s[9];
    __shared__ __align__(16) float f2sl[1320];
    __shared__ float ess2[336], ens2[336];
    __shared__ unsigned ams[440];
    __shared__ float tss[112], uss[112];
    const int b = blockIdx.x, tid = threadIdx.x, lane = tid & 31, wid = tid >> 5;

    for (int idx = tid; idx < 1080; idx += 128) w2s[idx] = W2[idx];
    if (tid < 9) { a2s[tid] = as2[tid]; n2s[tid] = an2[tid]; }
    for (int idx = tid; idx < 440; idx += 128) ams[idx] = g_am[b * 440 + idx];
    __syncthreads();

    // --- stage A: projection + logit halves (R10 k_proj2 inner; unroll 8 for MLP) ---
    if (tid < NN) {
        float acc[9];
#pragma unroll
        for (int j = 0; j < 9; j++) acc[j] = 0.f;
        const float* xp = g_h1T + (size_t)b * 13200 + tid;
#pragma unroll 8
        for (int k = 0; k < 120; k++) {
            float xv = xp[k * NN];
#pragma unroll
            for (int h2 = 0; h2 < 3; h2++) {
#pragma unroll
                for (int f2 = 0; f2 < 3; f2++)
                    acc[h2 * 3 + f2] = fmaf(xv, w2s[h2 * 360 + k * 3 + f2], acc[h2 * 3 + f2]);
            }
        }
#pragma unroll
        for (int h2 = 0; h2 < 3; h2++) {
            float e_s = 0.f, e_n = 0.f;
#pragma unroll
            for (int f2 = 0; f2 < 3; f2++) {
                e_s = fmaf(acc[h2 * 3 + f2], a2s[h2 * 3 + f2], e_s);
                e_n = fmaf(acc[h2 * 3 + f2], n2s[h2 * 3 + f2], e_n);
            }
            ess2[h2 * 112 + tid] = e_s;
            ens2[h2 * 112 + tid] = e_n;
            float4 o; o.x = acc[h2 * 3]; o.y = acc[h2 * 3 + 1]; o.z = acc[h2 * 3 + 2]; o.w = 0.f;
            *(float4*)(f2sl + (h2 * NN + tid) * 4) = o;
        }
    }
    __syncthreads();

    // --- stage B: sparse layer-2 attention + node probs (R10 k_tail inner, verbatim) ---
    if (tid < NN) {
        const int n = tid;
        float tot0 = 0.f, tot1 = 0.f, tot2 = 0.f;
#pragma unroll
        for (int h2 = 0; h2 < 3; h2++) {
            const float es = ess2[h2 * 112 + n];
            const float* ens = ens2 + h2 * 112;
            const ulonglong2* fbw = (const ulonglong2*)(f2sl + h2 * 440);
            u64 a0 = 0ull, a1 = 0ull;
            float sum = 0.f;
#pragma unroll
            for (int k = 0; k < 4; k++) {
                unsigned mw = ams[n * 4 + k];
                while (mw) {
                    const int m2 = __ffs(mw) - 1;
                    mw &= (mw - 1);
                    const int m = k * 32 + m2;
                    float v = es + ens[m];
                    v = v > 0.f ? v : ALPHA * v;
                    const float e = __expf(v);
                    sum += e;
                    const u64 s = splat2(e);
                    ulonglong2 w = fbw[m];
                    a0 = ffma2(s, w.x, a0);
                    a1 = ffma2(s, w.y, a1);
                }
            }
            const float rinv = 1.f / sum;
            float2 v0 = unpack2(a0), v1 = unpack2(a1);
            tot0 = fmaf(v0.x, rinv, tot0);
            tot1 = fmaf(v0.y, rinv, tot1);
            tot2 = fmaf(v1.x, rinv, tot2);
        }
        float z = lrelu(fmaf(tot0, (1.f / 3.f), b2[0])) * fc1[0]
                + lrelu(fmaf(tot1, (1.f / 3.f), b2[1])) * fc1[1]
                + lrelu(fmaf(tot2, (1.f / 3.f), b2[2])) * fc1[2];
        tss[tid] = sigm(z);
    }
    __syncthreads();

    // --- stage C: MIL pooling ---
    if (tid < NN) {
        const int m = tid;
        float s = 0.f;
#pragma unroll 4
        for (int n2 = 0; n2 < NN; n2++) s = fmaf(tss[n2], fc2[n2 * NN + m], s);
        uss[m] = s;
    }
    __syncthreads();
    if (wid == 0) {
        float vmax = -3.4e38f;
        for (int m = lane; m < NN; m += 32) vmax = fmaxf(vmax, uss[m]);
        vmax = warp_max(vmax);
        float num = 0.f, den = 0.f;
        for (int m = lane; m < NN; m += 32) {
            float e = __expf(uss[m] - vmax);
            num = fmaf(tss[m], e, num);
            den += e;
        }
        num = warp_sum(num);
        den = warp_sum(den);
        if (lane == 0) out[b] = num / den;
    }
}

extern "C" void kernel_launch(void* const* d_in, const int* in_sizes, int n_in,
                              void* d_out, int out_size)
{
    const float* X   = (const float*)d_in[0];
    const float* A   = (const float*)d_in[1];
    const float* M   = (const float*)d_in[2];
    const float* W1  = (const float*)d_in[3];
    const float* as1 = (const float*)d_in[4];
    const float* an1 = (const float*)d_in[5];
    const float* b1  = (const float*)d_in[6];
    const float* W2  = (const float*)d_in[7];
    const float* as2 = (const float*)d_in[8];
    const float* an2 = (const float*)d_in[9];
    const float* b2  = (const float*)d_in[10];
    const float* fc1 = (const float*)d_in[11];
    const float* fc2 = (const float*)d_in[12];
    float* out = (float*)d_out;

    const int B = in_sizes[0] / (NN * NN);

    k_prep<<<B, 256>>>(X, M, A);
    k_layer1<<<dim3(B, 5), 128>>>(W1, as1, an1, b1);
    k_layer2<<<B, 128>>>(W2, as2, an2, b2, fc1, fc2, out);
}